// round 1
// baseline (speedup 1.0000x reference)
#include <cuda_runtime.h>
#include <cuda_bf16.h>
#include <math.h>

// ---------------------------------------------------------------------------
// Problem constants
// ---------------------------------------------------------------------------
#define BGR   16384            // graphs
#define NPG   9                // nodes per graph
#define NNODE (BGR * NPG)      // 147456
#define DMODEL 128
#define DFF    512
#define NLAYER 4
#define EPG    16

// GEMM tiling
#define MC       64
#define NC       128
#define NTHREADS 128
#define SA_LD    132                       // smem lda for A tile (conflict-free)
#define SMEM_FLOATS (NC * DMODEL + MC * SA_LD)   // 16384 + 8448 = 24832
#define SMEM_BYTES  (SMEM_FLOATS * 4)            // 99328

// ---------------------------------------------------------------------------
// Scratch (device globals; no runtime allocation allowed)
// ---------------------------------------------------------------------------
__device__ float g_h  [(size_t)NNODE * DMODEL];   // 75.5 MB activations
__device__ float g_agg[(size_t)NNODE * DMODEL];   // 75.5 MB aggregated
__device__ float g_mid[(size_t)NNODE * DFF];      // 302 MB FFN mid
__device__ float g_inv[NNODE];                    // 1/sqrt(deg)

typedef unsigned long long ull;

// ---------------------------------------------------------------------------
// f32x2 packed-FMA helpers (sm_100+)
// ---------------------------------------------------------------------------
__device__ __forceinline__ ull pk2(float x, float y) {
    ull r;
    asm("mov.b64 %0, {%1, %2};" : "=l"(r) : "f"(x), "f"(y));
    return r;
}
__device__ __forceinline__ void upk2(ull v, float &x, float &y) {
    asm("mov.b64 {%0, %1}, %2;" : "=f"(x), "=f"(y) : "l"(v));
}
__device__ __forceinline__ void fma2(ull &c, ull a, ull b) {
    asm("fma.rn.f32x2 %0, %1, %2, %0;" : "+l"(c) : "l"(a), "l"(b));
}

// ---------------------------------------------------------------------------
// Tile loaders
// ---------------------------------------------------------------------------
// A tile: rows [m0, m0+64), cols [k0, k0+128) of row-major A (lda_g), into
// sA[m][k] with stride SA_LD (row stride 132 floats -> bank-conflict-free
// broadcast fragment loads AND 16B-aligned float4 stores).
__device__ __forceinline__ void load_A_tile(const float* __restrict__ A, int lda_g,
                                            int m0, int k0, float* sA, int tid) {
#pragma unroll
    for (int i = 0; i < 16; i++) {
        int f4 = tid + NTHREADS * i;       // 2048 float4s
        int m  = f4 >> 5;                  // same m across a warp
        int c4 = f4 & 31;                  // = lane
        float4 v = *reinterpret_cast<const float4*>(
            A + (size_t)(m0 + m) * lda_g + k0 + c4 * 4);
        *reinterpret_cast<float4*>(sA + m * SA_LD + c4 * 4) = v;
    }
}

// W tile: rows [k0, k0+128), cols [n0, n0+128) of row-major W (ldw_g), into
// sW[k][n] stride 128.
__device__ __forceinline__ void load_W_tile(const float* __restrict__ W, int ldw_g,
                                            int k0, int n0, float* sW, int tid) {
#pragma unroll
    for (int i = 0; i < 32; i++) {
        int f4 = tid + NTHREADS * i;       // 4096 float4s
        int k  = f4 >> 5;
        int c4 = f4 & 31;
        float4 v = *reinterpret_cast<const float4*>(
            W + (size_t)(k0 + k) * ldw_g + n0 + c4 * 4);
        *reinterpret_cast<float4*>(sW + k * NC + c4 * 4) = v;
    }
}

// ---------------------------------------------------------------------------
// Core 64x128 += 64x128 @ 128x128, per-thread 8x8 micro-tile via f32x2.
// tm = tid&7 -> rows {tm + 8i}; tn = tid>>3 -> cols [tn*8, tn*8+8).
// ---------------------------------------------------------------------------
__device__ __forceinline__ void gemm128(const float* __restrict__ sA,
                                        const float* __restrict__ sW,
                                        int tm, int tn, ull acc[8][4]) {
#pragma unroll 8
    for (int k = 0; k < DMODEL; k++) {
        float4 b0 = *reinterpret_cast<const float4*>(sW + k * NC + tn * 8);
        float4 b1 = *reinterpret_cast<const float4*>(sW + k * NC + tn * 8 + 4);
        ull bv0 = pk2(b0.x, b0.y), bv1 = pk2(b0.z, b0.w);
        ull bv2 = pk2(b1.x, b1.y), bv3 = pk2(b1.z, b1.w);
#pragma unroll
        for (int i = 0; i < 8; i++) {
            float a = sA[(tm + 8 * i) * SA_LD + k];
            ull av = pk2(a, a);
            fma2(acc[i][0], av, bv0);
            fma2(acc[i][1], av, bv1);
            fma2(acc[i][2], av, bv2);
            fma2(acc[i][3], av, bv3);
        }
    }
}

__device__ __forceinline__ void init_acc_bias(const float* __restrict__ bias,
                                              int n_off, int tn, ull acc[8][4]) {
    float4 bb0 = *reinterpret_cast<const float4*>(bias + n_off + tn * 8);
    float4 bb1 = *reinterpret_cast<const float4*>(bias + n_off + tn * 8 + 4);
    ull i0 = pk2(bb0.x, bb0.y), i1 = pk2(bb0.z, bb0.w);
    ull i2 = pk2(bb1.x, bb1.y), i3 = pk2(bb1.z, bb1.w);
#pragma unroll
    for (int i = 0; i < 8; i++) {
        acc[i][0] = i0; acc[i][1] = i1; acc[i][2] = i2; acc[i][3] = i3;
    }
}

// ---------------------------------------------------------------------------
// K0: degree -> inv_sqrt_deg  (one thread per graph; in-degree + self loop)
// ---------------------------------------------------------------------------
__global__ void deg_kernel(const int* __restrict__ dst) {
    int g = blockIdx.x * blockDim.x + threadIdx.x;
    if (g >= BGR) return;
    int base = g * NPG;
    int cnt[NPG];
#pragma unroll
    for (int j = 0; j < NPG; j++) cnt[j] = 1;   // self loop
#pragma unroll
    for (int e = 0; e < EPG; e++) {
        int dl = dst[g * EPG + e] - base;
#pragma unroll
        for (int j = 0; j < NPG; j++) cnt[j] += (dl == j) ? 1 : 0;
    }
#pragma unroll
    for (int j = 0; j < NPG; j++)
        g_inv[base + j] = rsqrtf((float)cnt[j]);
}

// ---------------------------------------------------------------------------
// K1: embedding  h[n] = op_table[op_idx[n]] + device_emb
// ---------------------------------------------------------------------------
__global__ void embed_kernel(const float4* __restrict__ opt,
                             const float4* __restrict__ de,
                             const int* __restrict__ op_idx) {
    int idx = blockIdx.x * blockDim.x + threadIdx.x;   // < NNODE*32
    int n = idx >> 5, c = idx & 31;
    int op = op_idx[n];
    float4 t = opt[op * 32 + c];
    float4 d = de[c];
    float4 o = make_float4(t.x + d.x, t.y + d.y, t.z + d.z, t.w + d.w);
    reinterpret_cast<float4*>(g_h)[idx] = o;
}

// ---------------------------------------------------------------------------
// K2: per-graph symmetric-normalized aggregation (no atomics; 1 block/graph)
// ---------------------------------------------------------------------------
__global__ __launch_bounds__(128) void agg_kernel(const int* __restrict__ src,
                                                  const int* __restrict__ dst) {
    __shared__ float hs[NPG * DMODEL];
    __shared__ float ag[NPG * DMODEL];
    __shared__ float invs[NPG];
    __shared__ float we[EPG];
    __shared__ int sl[EPG], dl[EPG];

    int g = blockIdx.x, t = threadIdx.x;
    int nbase = g * NPG;
    if (t < NPG) invs[t] = g_inv[nbase + t];
    if (t < EPG) {
        sl[t] = src[g * EPG + t] - nbase;
        dl[t] = dst[g * EPG + t] - nbase;
    }
    __syncthreads();
    if (t < EPG) we[t] = invs[sl[t]] * invs[dl[t]];
#pragma unroll
    for (int j = 0; j < NPG; j++) {
        float v = g_h[(size_t)(nbase + j) * DMODEL + t];
        hs[j * DMODEL + t] = v;
        ag[j * DMODEL + t] = invs[j] * invs[j] * v;   // self loop term
    }
    __syncthreads();
#pragma unroll
    for (int e = 0; e < EPG; e++)
        ag[dl[e] * DMODEL + t] += we[e] * hs[sl[e] * DMODEL + t];
#pragma unroll
    for (int j = 0; j < NPG; j++)
        g_agg[(size_t)(nbase + j) * DMODEL + t] = ag[j * DMODEL + t];
}

// ---------------------------------------------------------------------------
// K3: GCN GEMM + bias + relu + LayerNorm :  g_h = LN(relu(g_agg @ Wg + bg))
// ---------------------------------------------------------------------------
__global__ __launch_bounds__(NTHREADS) void gcn_kernel(const float* __restrict__ W,
                                                       const float* __restrict__ bias,
                                                       const float* __restrict__ lng,
                                                       const float* __restrict__ lnb) {
    extern __shared__ float smem[];
    float* sW = smem;
    float* sA = smem + NC * DMODEL;
    int tid = threadIdx.x;
    int tm = tid & 7, tn = tid >> 3;
    int m0 = blockIdx.x * MC;

    load_A_tile(g_agg, DMODEL, m0, 0, sA, tid);
    load_W_tile(W, DMODEL, 0, 0, sW, tid);

    ull acc[8][4];
    init_acc_bias(bias, 0, tn, acc);
    __syncthreads();
    gemm128(sA, sW, tm, tn, acc);
    __syncthreads();                      // everyone done reading sA

    // relu -> stage rows into sC (reuse sA region, stride 132)
    float* sC = sA;
#pragma unroll
    for (int i = 0; i < 8; i++) {
        int r = tm + 8 * i;
        float c0, c1, c2, c3, c4, c5, c6, c7;
        upk2(acc[i][0], c0, c1); upk2(acc[i][1], c2, c3);
        upk2(acc[i][2], c4, c5); upk2(acc[i][3], c6, c7);
        float4 o0 = make_float4(fmaxf(c0, 0.f), fmaxf(c1, 0.f), fmaxf(c2, 0.f), fmaxf(c3, 0.f));
        float4 o1 = make_float4(fmaxf(c4, 0.f), fmaxf(c5, 0.f), fmaxf(c6, 0.f), fmaxf(c7, 0.f));
        *reinterpret_cast<float4*>(sC + r * SA_LD + tn * 8)     = o0;
        *reinterpret_cast<float4*>(sC + r * SA_LD + tn * 8 + 4) = o1;
    }
    __syncthreads();

    // LayerNorm: one warp per row (each warp handles 16 rows)
    int w = tid >> 5, lane = tid & 31;
    float4 gq = *reinterpret_cast<const float4*>(lng + lane * 4);
    float4 bq = *reinterpret_cast<const float4*>(lnb + lane * 4);
    for (int it = 0; it < 16; it++) {
        int r = w * 16 + it;
        float4 x = *reinterpret_cast<const float4*>(sC + r * SA_LD + lane * 4);
        float s = x.x + x.y + x.z + x.w;
#pragma unroll
        for (int o = 16; o; o >>= 1) s += __shfl_xor_sync(0xffffffffu, s, o);
        float mu = s * (1.f / 128.f);
        float dx = x.x - mu, dy = x.y - mu, dz = x.z - mu, dw = x.w - mu;
        float q = dx * dx + dy * dy + dz * dz + dw * dw;
#pragma unroll
        for (int o = 16; o; o >>= 1) q += __shfl_xor_sync(0xffffffffu, q, o);
        float rs = rsqrtf(q * (1.f / 128.f) + 1e-5f);
        float4 o4 = make_float4(dx * rs * gq.x + bq.x, dy * rs * gq.y + bq.y,
                                dz * rs * gq.z + bq.z, dw * rs * gq.w + bq.w);
        *reinterpret_cast<float4*>(g_h + (size_t)(m0 + r) * DMODEL + lane * 4) = o4;
    }
}

// ---------------------------------------------------------------------------
// K4: FFN1 :  g_mid[:, n0:n0+128] = relu(g_h @ W1[:, n0:n0+128] + b1)
// ---------------------------------------------------------------------------
__global__ __launch_bounds__(NTHREADS) void ffn1_kernel(const float* __restrict__ W1l,
                                                        const float* __restrict__ b1l) {
    extern __shared__ float smem[];
    float* sW = smem;
    float* sA = smem + NC * DMODEL;
    int tid = threadIdx.x;
    int tm = tid & 7, tn = tid >> 3;
    int m0 = blockIdx.x * MC;
    int n0 = blockIdx.y * NC;

    load_A_tile(g_h, DMODEL, m0, 0, sA, tid);
    load_W_tile(W1l, DFF, 0, n0, sW, tid);

    ull acc[8][4];
    init_acc_bias(b1l, n0, tn, acc);
    __syncthreads();
    gemm128(sA, sW, tm, tn, acc);

#pragma unroll
    for (int i = 0; i < 8; i++) {
        int row = m0 + tm + 8 * i;
        float c0, c1, c2, c3, c4, c5, c6, c7;
        upk2(acc[i][0], c0, c1); upk2(acc[i][1], c2, c3);
        upk2(acc[i][2], c4, c5); upk2(acc[i][3], c6, c7);
        float4 o0 = make_float4(fmaxf(c0, 0.f), fmaxf(c1, 0.f), fmaxf(c2, 0.f), fmaxf(c3, 0.f));
        float4 o1 = make_float4(fmaxf(c4, 0.f), fmaxf(c5, 0.f), fmaxf(c6, 0.f), fmaxf(c7, 0.f));
        float* p = g_mid + (size_t)row * DFF + n0 + tn * 8;
        *reinterpret_cast<float4*>(p)     = o0;
        *reinterpret_cast<float4*>(p + 4) = o1;
    }
}

// ---------------------------------------------------------------------------
// K5: FFN2 :  g_h = g_h + g_mid @ W2 + b2   (K = 512 in 4 chunks)
// ---------------------------------------------------------------------------
__global__ __launch_bounds__(NTHREADS) void ffn2_kernel(const float* __restrict__ W2l,
                                                        const float* __restrict__ b2l) {
    extern __shared__ float smem[];
    float* sW = smem;
    float* sA = smem + NC * DMODEL;
    int tid = threadIdx.x;
    int tm = tid & 7, tn = tid >> 3;
    int m0 = blockIdx.x * MC;

    ull acc[8][4];
    init_acc_bias(b2l, 0, tn, acc);

    for (int kc = 0; kc < 4; kc++) {
        __syncthreads();
        load_A_tile(g_mid, DFF, m0, kc * DMODEL, sA, tid);
        load_W_tile(W2l, DMODEL, kc * DMODEL, 0, sW, tid);
        __syncthreads();
        gemm128(sA, sW, tm, tn, acc);
    }

#pragma unroll
    for (int i = 0; i < 8; i++) {
        int row = m0 + tm + 8 * i;
        float c0, c1, c2, c3, c4, c5, c6, c7;
        upk2(acc[i][0], c0, c1); upk2(acc[i][1], c2, c3);
        upk2(acc[i][2], c4, c5); upk2(acc[i][3], c6, c7);
        float* p = g_h + (size_t)row * DMODEL + tn * 8;
        float4 r0 = *reinterpret_cast<const float4*>(p);
        float4 r1 = *reinterpret_cast<const float4*>(p + 4);
        float4 o0 = make_float4(c0 + r0.x, c1 + r0.y, c2 + r0.z, c3 + r0.w);
        float4 o1 = make_float4(c4 + r1.x, c5 + r1.y, c6 + r1.z, c7 + r1.w);
        *reinterpret_cast<float4*>(p)     = o0;
        *reinterpret_cast<float4*>(p + 4) = o1;
    }
}

// ---------------------------------------------------------------------------
// K6: readout  out[g] = sigmoid(mean_j(h[g,j,:]) . fc_w + fc_b)
// ---------------------------------------------------------------------------
__global__ __launch_bounds__(128) void readout_kernel(const float4* __restrict__ fcw,
                                                      const float* __restrict__ fcb,
                                                      float* __restrict__ out) {
    int w = threadIdx.x >> 5, lane = threadIdx.x & 31;
    int g = blockIdx.x * 4 + w;
    const float4* h4 = reinterpret_cast<const float4*>(g_h);
    size_t base = (size_t)g * NPG * 32;
    float4 s = make_float4(0.f, 0.f, 0.f, 0.f);
#pragma unroll
    for (int j = 0; j < NPG; j++) {
        float4 v = h4[base + j * 32 + lane];
        s.x += v.x; s.y += v.y; s.z += v.z; s.w += v.w;
    }
    float4 wv = fcw[lane];
    float p = s.x * wv.x + s.y * wv.y + s.z * wv.z + s.w * wv.w;
#pragma unroll
    for (int o = 16; o; o >>= 1) p += __shfl_xor_sync(0xffffffffu, p, o);
    if (lane == 0)
        out[g] = 1.f / (1.f + expf(-(p * (1.f / 9.f) + fcb[0])));
}

// ---------------------------------------------------------------------------
// Launcher
// ---------------------------------------------------------------------------
extern "C" void kernel_launch(void* const* d_in, const int* in_sizes, int n_in,
                              void* d_out, int out_size) {
    const float* op_table   = (const float*)d_in[0];
    const float* device_emb = (const float*)d_in[1];
    const float* Wg         = (const float*)d_in[2];
    const float* bg         = (const float*)d_in[3];
    const float* ln_g       = (const float*)d_in[4];
    const float* ln_b       = (const float*)d_in[5];
    const float* W1         = (const float*)d_in[6];
    const float* b1         = (const float*)d_in[7];
    const float* W2         = (const float*)d_in[8];
    const float* b2         = (const float*)d_in[9];
    const float* fc_w       = (const float*)d_in[10];
    const float* fc_b       = (const float*)d_in[11];
    const int*   op_idx     = (const int*)d_in[12];
    const int*   src        = (const int*)d_in[13];
    const int*   dst        = (const int*)d_in[14];
    float* out = (float*)d_out;

    cudaFuncSetAttribute(gcn_kernel,  cudaFuncAttributeMaxDynamicSharedMemorySize, SMEM_BYTES);
    cudaFuncSetAttribute(ffn1_kernel, cudaFuncAttributeMaxDynamicSharedMemorySize, SMEM_BYTES);
    cudaFuncSetAttribute(ffn2_kernel, cudaFuncAttributeMaxDynamicSharedMemorySize, SMEM_BYTES);

    deg_kernel<<<BGR / 256, 256>>>(dst);
    embed_kernel<<<(NNODE * 32) / 256, 256>>>(
        (const float4*)op_table, (const float4*)device_emb, op_idx);

    for (int l = 0; l < NLAYER; l++) {
        agg_kernel<<<BGR, 128>>>(src, dst);
        gcn_kernel<<<NNODE / MC, NTHREADS, SMEM_BYTES>>>(
            Wg + (size_t)l * DMODEL * DMODEL, bg + l * DMODEL,
            ln_g + l * DMODEL, ln_b + l * DMODEL);
        ffn1_kernel<<<dim3(NNODE / MC, DFF / NC), NTHREADS, SMEM_BYTES>>>(
            W1 + (size_t)l * DMODEL * DFF, b1 + l * DFF);
        ffn2_kernel<<<NNODE / MC, NTHREADS, SMEM_BYTES>>>(
            W2 + (size_t)l * DFF * DMODEL, b2 + l * DMODEL);
    }

    readout_kernel<<<BGR / 4, 128>>>((const float4*)fc_w, fc_b, out);
}